// round 1
// baseline (speedup 1.0000x reference)
#include <cuda_runtime.h>

#define B_ 4
#define C_ 256
#define N_ 2048
#define H_ 8
#define D_ 32

// Scratch (allocation-free rule: __device__ globals)
__device__ float g_Q[B_*C_*N_];   // [B,H,D,N], pre-scaled by D^-0.5
__device__ float g_K[B_*C_*N_];   // [B,H,D,N]
__device__ float g_V[B_*C_*N_];   // [B,H,D,N]
__device__ float g_AO[B_*C_*N_];  // attention out, [B,C,N] (== [B,H,D,N])
__device__ float g_Y[B_*C_*N_];   // proj + bias + residual, [B,C,N]

// ---------------------------------------------------------------------------
// Kernel 1: QKV GEMM.  Y[o,n] = sum_c W[o,c] * x[b,c,n] + bias[o]
// 64x64 tile, BK=16, 256 threads, 4x4 microtile. Scatters rows to Q/K/V.
// ---------------------------------------------------------------------------
__global__ __launch_bounds__(256) void qkv_gemm_kernel(
    const float* __restrict__ x, const float* __restrict__ W,
    const float* __restrict__ bias)
{
    __shared__ float As[64][16];  // [m][k], store conflict-free, read near-broadcast
    __shared__ float Bs[16][64];  // [k][n], float4 reads

    const int b  = blockIdx.z;
    const int o0 = blockIdx.y * 64;
    const int n0 = blockIdx.x * 64;
    const int tid = threadIdx.x;
    const int tx = tid & 15, ty = tid >> 4;

    const float* xb = x + b * (C_ * N_);
    float acc[4][4] = {};

    for (int kk = 0; kk < C_; kk += 16) {
        #pragma unroll
        for (int i = 0; i < 4; i++) {
            int lin = tid + i * 256;
            int m = lin >> 4, k = lin & 15;
            As[m][k] = W[(o0 + m) * C_ + kk + k];
        }
        #pragma unroll
        for (int i = 0; i < 4; i++) {
            int lin = tid + i * 256;
            int k = lin >> 6, n = lin & 63;
            Bs[k][n] = xb[(kk + k) * N_ + n0 + n];
        }
        __syncthreads();
        #pragma unroll
        for (int k = 0; k < 16; k++) {
            float4 bv = *(const float4*)&Bs[k][tx * 4];
            #pragma unroll
            for (int i = 0; i < 4; i++) {
                float a = As[ty * 4 + i][k];
                acc[i][0] += a * bv.x;
                acc[i][1] += a * bv.y;
                acc[i][2] += a * bv.z;
                acc[i][3] += a * bv.w;
            }
        }
        __syncthreads();
    }

    const float qscale = 0.17677669529663687f;  // 1/sqrt(32)
    #pragma unroll
    for (int i = 0; i < 4; i++) {
        int o  = o0 + ty * 4 + i;
        int s  = o >> 8;        // 0=q, 1=k, 2=v
        int cd = o & 255;       // h*32 + d
        float bv = bias[o];
        float scale = (s == 0) ? qscale : 1.0f;
        float* base = (s == 0) ? g_Q : (s == 1) ? g_K : g_V;
        float* dst = base + b * (C_ * N_) + cd * N_ + n0 + tx * 4;
        float4 v;
        v.x = (acc[i][0] + bv) * scale;
        v.y = (acc[i][1] + bv) * scale;
        v.z = (acc[i][2] + bv) * scale;
        v.w = (acc[i][3] + bv) * scale;
        *(float4*)dst = v;
    }
}

// ---------------------------------------------------------------------------
// Kernel 2: Flash attention. Block = 128 query rows of one (b,h).
// One thread per query row; key/value tiles of 64 in smem, layout [j][d]
// with row stride 36 (float4-aligned), broadcast float4 reads.
// ---------------------------------------------------------------------------
__global__ __launch_bounds__(128) void attn_kernel()
{
    __shared__ float Ks[64][36];
    __shared__ float Vs[64][36];

    const int bh = blockIdx.y;                       // b*8 + h
    const int n  = blockIdx.x * 128 + threadIdx.x;   // query row
    const float* Qb = g_Q + bh * (D_ * N_);
    const float* Kb = g_K + bh * (D_ * N_);
    const float* Vb = g_V + bh * (D_ * N_);

    float q[32];
    #pragma unroll
    for (int d = 0; d < 32; d++) q[d] = Qb[d * N_ + n];

    float4 o4[8];
    #pragma unroll
    for (int i = 0; i < 8; i++) o4[i] = make_float4(0.f, 0.f, 0.f, 0.f);
    float m = -1e30f, l = 0.f;

    for (int t = 0; t < N_; t += 64) {
        // cooperative tile load: lanes sweep j (coalesced global reads)
        #pragma unroll
        for (int i = 0; i < 16; i++) {
            int lin = threadIdx.x + i * 128;
            int j = lin & 63, d = lin >> 6;
            Ks[j][d] = Kb[d * N_ + t + j];
            Vs[j][d] = Vb[d * N_ + t + j];
        }
        __syncthreads();

        float s[64];
        float mt = m;
        #pragma unroll
        for (int j = 0; j < 64; j++) {
            const float4* kr = (const float4*)Ks[j];
            float acc = 0.f;
            #pragma unroll
            for (int d4 = 0; d4 < 8; d4++) {
                float4 k4 = kr[d4];
                acc += q[d4 * 4 + 0] * k4.x;
                acc += q[d4 * 4 + 1] * k4.y;
                acc += q[d4 * 4 + 2] * k4.z;
                acc += q[d4 * 4 + 3] * k4.w;
            }
            s[j] = acc;
            mt = fmaxf(mt, acc);
        }

        float corr = __expf(m - mt);
        l *= corr;
        #pragma unroll
        for (int i = 0; i < 8; i++) {
            o4[i].x *= corr; o4[i].y *= corr; o4[i].z *= corr; o4[i].w *= corr;
        }

        #pragma unroll
        for (int j = 0; j < 64; j++) {
            float p = __expf(s[j] - mt);
            l += p;
            const float4* vr = (const float4*)Vs[j];
            #pragma unroll
            for (int i = 0; i < 8; i++) {
                float4 v = vr[i];
                o4[i].x += p * v.x;
                o4[i].y += p * v.y;
                o4[i].z += p * v.z;
                o4[i].w += p * v.w;
            }
        }
        m = mt;
        __syncthreads();
    }

    float inv = 1.f / l;
    float* AOb = g_AO + bh * (D_ * N_);
    #pragma unroll
    for (int i = 0; i < 8; i++) {
        AOb[(i * 4 + 0) * N_ + n] = o4[i].x * inv;
        AOb[(i * 4 + 1) * N_ + n] = o4[i].y * inv;
        AOb[(i * 4 + 2) * N_ + n] = o4[i].z * inv;
        AOb[(i * 4 + 3) * N_ + n] = o4[i].w * inv;
    }
}

// ---------------------------------------------------------------------------
// Kernel 3: proj GEMM + bias + residual.  Y = Wp @ AO + bp + x
// ---------------------------------------------------------------------------
__global__ __launch_bounds__(256) void proj_gemm_kernel(
    const float* __restrict__ x, const float* __restrict__ W,
    const float* __restrict__ bias)
{
    __shared__ float As[64][16];
    __shared__ float Bs[16][64];

    const int b  = blockIdx.z;
    const int o0 = blockIdx.y * 64;
    const int n0 = blockIdx.x * 64;
    const int tid = threadIdx.x;
    const int tx = tid & 15, ty = tid >> 4;

    const float* ab = g_AO + b * (C_ * N_);
    float acc[4][4] = {};

    for (int kk = 0; kk < C_; kk += 16) {
        #pragma unroll
        for (int i = 0; i < 4; i++) {
            int lin = tid + i * 256;
            int m = lin >> 4, k = lin & 15;
            As[m][k] = W[(o0 + m) * C_ + kk + k];
        }
        #pragma unroll
        for (int i = 0; i < 4; i++) {
            int lin = tid + i * 256;
            int k = lin >> 6, n = lin & 63;
            Bs[k][n] = ab[(kk + k) * N_ + n0 + n];
        }
        __syncthreads();
        #pragma unroll
        for (int k = 0; k < 16; k++) {
            float4 bv = *(const float4*)&Bs[k][tx * 4];
            #pragma unroll
            for (int i = 0; i < 4; i++) {
                float a = As[ty * 4 + i][k];
                acc[i][0] += a * bv.x;
                acc[i][1] += a * bv.y;
                acc[i][2] += a * bv.z;
                acc[i][3] += a * bv.w;
            }
        }
        __syncthreads();
    }

    #pragma unroll
    for (int i = 0; i < 4; i++) {
        int o = o0 + ty * 4 + i;
        float bv = bias[o];
        const float* xr = x + b * (C_ * N_) + o * N_ + n0 + tx * 4;
        float4 xr4 = *(const float4*)xr;
        float* dst = g_Y + b * (C_ * N_) + o * N_ + n0 + tx * 4;
        float4 v;
        v.x = acc[i][0] + bv + xr4.x;
        v.y = acc[i][1] + bv + xr4.y;
        v.z = acc[i][2] + bv + xr4.z;
        v.w = acc[i][3] + bv + xr4.w;
        *(float4*)dst = v;
    }
}

// ---------------------------------------------------------------------------
// Kernel 4: LayerNorm over channels. 1 thread per (b,n) column, two coalesced
// passes over Y (second pass L2-hot).
// ---------------------------------------------------------------------------
__global__ __launch_bounds__(128) void ln_kernel(
    const float* __restrict__ ln_g, const float* __restrict__ ln_b,
    float* __restrict__ out)
{
    const int b = blockIdx.y;
    const int n = blockIdx.x * 128 + threadIdx.x;
    const float* Yb = g_Y + b * (C_ * N_) + n;

    float sum = 0.f, sumsq = 0.f;
    #pragma unroll 8
    for (int c = 0; c < C_; c++) {
        float v = Yb[c * N_];
        sum += v;
        sumsq += v * v;
    }
    float mu   = sum * (1.f / C_);
    float var  = sumsq * (1.f / C_) - mu * mu;
    float rstd = rsqrtf(var + 1e-5f);

    float* ob = out + b * (C_ * N_) + n;
    #pragma unroll 8
    for (int c = 0; c < C_; c++) {
        float v = Yb[c * N_];
        ob[c * N_] = (v - mu) * rstd * ln_g[c] + ln_b[c];
    }
}

// ---------------------------------------------------------------------------
extern "C" void kernel_launch(void* const* d_in, const int* in_sizes, int n_in,
                              void* d_out, int out_size)
{
    const float* x      = (const float*)d_in[0];
    const float* w_qkv  = (const float*)d_in[1];
    const float* b_qkv  = (const float*)d_in[2];
    const float* w_proj = (const float*)d_in[3];
    const float* b_proj = (const float*)d_in[4];
    const float* ln_g   = (const float*)d_in[5];
    const float* ln_b   = (const float*)d_in[6];
    float* out = (float*)d_out;

    qkv_gemm_kernel<<<dim3(N_ / 64, (3 * C_) / 64, B_), 256>>>(x, w_qkv, b_qkv);
    attn_kernel<<<dim3(N_ / 128, B_ * H_), 128>>>();
    proj_gemm_kernel<<<dim3(N_ / 64, C_ / 64, B_), 256>>>(x, w_proj, b_proj);
    ln_kernel<<<dim3(N_ / 128, B_), 128>>>(ln_g, ln_b, out);
}

// round 2
// speedup vs baseline: 2.3933x; 2.3933x over previous
#include <cuda_runtime.h>

#define B_ 4
#define C_ 256
#define N_ 2048
#define H_ 8
#define D_ 32

// Scratch (allocation-free rule: __device__ globals)
__device__ float g_Q[B_*C_*N_];   // [B,H,D,N], pre-scaled by D^-0.5
__device__ float g_K[B_*C_*N_];   // [B,H,D,N]
__device__ float g_V[B_*C_*N_];   // [B,H,D,N]
__device__ float g_AO[B_*C_*N_];  // attention out, [B,C,N]
__device__ float g_Y[B_*C_*N_];   // proj + bias + residual, [B,C,N]

__device__ __forceinline__ float f2tf32(float f) {
    unsigned u;
    asm("cvt.rna.tf32.f32 %0, %1;" : "=r"(u) : "f"(f));
    return __uint_as_float(u);
}

__device__ __forceinline__ void mma_tf32(float* d, unsigned a0, unsigned a1,
                                         unsigned a2, unsigned a3,
                                         unsigned b0, unsigned b1) {
    asm volatile(
        "mma.sync.aligned.m16n8k8.row.col.f32.tf32.tf32.f32 "
        "{%0,%1,%2,%3}, {%4,%5,%6,%7}, {%8,%9}, {%0,%1,%2,%3};\n"
        : "+f"(d[0]), "+f"(d[1]), "+f"(d[2]), "+f"(d[3])
        : "r"(a0), "r"(a1), "r"(a2), "r"(a3), "r"(b0), "r"(b1));
}

// ---------------------------------------------------------------------------
// Kernel 1: QKV GEMM.  Y[o,n] = sum_c W[o,c] * x[b,c,n] + bias[o]
// ---------------------------------------------------------------------------
__global__ __launch_bounds__(256) void qkv_gemm_kernel(
    const float* __restrict__ x, const float* __restrict__ W,
    const float* __restrict__ bias)
{
    __shared__ float As[64][16];
    __shared__ float Bs[16][64];

    const int b  = blockIdx.z;
    const int o0 = blockIdx.y * 64;
    const int n0 = blockIdx.x * 64;
    const int tid = threadIdx.x;
    const int tx = tid & 15, ty = tid >> 4;

    const float* xb = x + b * (C_ * N_);
    float acc[4][4] = {};

    for (int kk = 0; kk < C_; kk += 16) {
        #pragma unroll
        for (int i = 0; i < 4; i++) {
            int lin = tid + i * 256;
            int m = lin >> 4, k = lin & 15;
            As[m][k] = W[(o0 + m) * C_ + kk + k];
        }
        #pragma unroll
        for (int i = 0; i < 4; i++) {
            int lin = tid + i * 256;
            int k = lin >> 6, n = lin & 63;
            Bs[k][n] = xb[(kk + k) * N_ + n0 + n];
        }
        __syncthreads();
        #pragma unroll
        for (int k = 0; k < 16; k++) {
            float4 bv = *(const float4*)&Bs[k][tx * 4];
            #pragma unroll
            for (int i = 0; i < 4; i++) {
                float a = As[ty * 4 + i][k];
                acc[i][0] += a * bv.x;
                acc[i][1] += a * bv.y;
                acc[i][2] += a * bv.z;
                acc[i][3] += a * bv.w;
            }
        }
        __syncthreads();
    }

    const float qscale = 0.17677669529663687f;  // 1/sqrt(32)
    #pragma unroll
    for (int i = 0; i < 4; i++) {
        int o  = o0 + ty * 4 + i;
        int s  = o >> 8;
        int cd = o & 255;
        float bv = bias[o];
        float scale = (s == 0) ? qscale : 1.0f;
        float* base = (s == 0) ? g_Q : (s == 1) ? g_K : g_V;
        float* dst = base + b * (C_ * N_) + cd * N_ + n0 + tx * 4;
        float4 v;
        v.x = (acc[i][0] + bv) * scale;
        v.y = (acc[i][1] + bv) * scale;
        v.z = (acc[i][2] + bv) * scale;
        v.w = (acc[i][3] + bv) * scale;
        *(float4*)dst = v;
    }
}

// ---------------------------------------------------------------------------
// Kernel 2: Flash attention on tf32 tensor cores (mma.m16n8k8).
// CTA: 128 query rows of one (b,h); 4 warps x 32 rows. Key tiles of 64.
// ---------------------------------------------------------------------------
#define QPAD 37
#define KPAD 37
#define PPAD 68
#define OPAD 132
// smem float offsets
#define QS_OFF 0
#define KS_OFF (128*QPAD)                 // 4736
#define VS_OFF (KS_OFF + 64*KPAD)         // +2368
#define PS_OFF (VS_OFF + 64*KPAD)         // +2368
#define SMEM_FLOATS (PS_OFF + 128*PPAD)   // +8704 = 18176 floats = 72704 B

__global__ __launch_bounds__(128) void attn_kernel()
{
    extern __shared__ float sm[];
    float* Qs = sm + QS_OFF;   // [128][QPAD], tf32; aliased as Os[32][OPAD] in epilogue
    float* Ks = sm + KS_OFF;   // [64][KPAD], tf32
    float* Vs = sm + VS_OFF;   // [64][KPAD], tf32
    float* Ps = sm + PS_OFF;   // [128][PPAD], tf32 (warp-private row ranges)

    const int bh   = blockIdx.y;
    const int n0   = blockIdx.x * 128;
    const int tid  = threadIdx.x;
    const int warp = tid >> 5;
    const int lane = tid & 31;
    const int g    = lane >> 2;   // groupID
    const int q    = lane & 3;    // threadID_in_group

    const float* Qb = g_Q + bh * (D_ * N_);
    const float* Kb = g_K + bh * (D_ * N_);
    const float* Vb = g_V + bh * (D_ * N_);

    // Stage Q tile [128 rows][32 d] as tf32
    #pragma unroll
    for (int i = 0; i < 32; i++) {
        int lin = tid + i * 128;
        int n = lin & 127, dd = lin >> 7;
        Qs[n * QPAD + dd] = f2tf32(Qb[dd * N_ + n0 + n]);
    }
    __syncthreads();

    // Q fragments: qa[mi][kc][4];  rows warp*32 + mi*16 + {g, g+8}, cols kc*8 + {q, q+4}
    unsigned qa[2][4][4];
    #pragma unroll
    for (int mi = 0; mi < 2; mi++) {
        int r = warp * 32 + mi * 16 + g;
        #pragma unroll
        for (int kc = 0; kc < 4; kc++) {
            qa[mi][kc][0] = __float_as_uint(Qs[r * QPAD + kc * 8 + q]);
            qa[mi][kc][1] = __float_as_uint(Qs[(r + 8) * QPAD + kc * 8 + q]);
            qa[mi][kc][2] = __float_as_uint(Qs[r * QPAD + kc * 8 + q + 4]);
            qa[mi][kc][3] = __float_as_uint(Qs[(r + 8) * QPAD + kc * 8 + q + 4]);
        }
    }

    float o[2][4][4] = {};        // output accum: rows {g,g+8} per mi, cols d = ni*8+2q+{0,1}
    float mrow[4] = {-1e30f, -1e30f, -1e30f, -1e30f};  // [mi*2+half]
    float lrow[4] = {};           // per-thread partial row sums (quad-reduced at end)

    for (int t = 0; t < N_; t += 64) {
        __syncthreads();
        // Stage K/V tile [64 j][32 d] as tf32 (coalesced gmem, conflict-free STS: pad 37)
        #pragma unroll
        for (int i = 0; i < 16; i++) {
            int lin = tid + i * 128;
            int j = lin & 63, dd = lin >> 6;
            Ks[j * KPAD + dd] = f2tf32(Kb[dd * N_ + t + j]);
            Vs[j * KPAD + dd] = f2tf32(Vb[dd * N_ + t + j]);
        }
        __syncthreads();

        // S = Q * K^T : per warp 32 rows x 64 cols
        float s[2][8][4] = {};
        #pragma unroll
        for (int kc = 0; kc < 4; kc++) {
            #pragma unroll
            for (int ni = 0; ni < 8; ni++) {
                unsigned b0 = __float_as_uint(Ks[(ni * 8 + g) * KPAD + kc * 8 + q]);
                unsigned b1 = __float_as_uint(Ks[(ni * 8 + g) * KPAD + kc * 8 + q + 4]);
                mma_tf32(s[0][ni], qa[0][kc][0], qa[0][kc][1], qa[0][kc][2], qa[0][kc][3], b0, b1);
                mma_tf32(s[1][ni], qa[1][kc][0], qa[1][kc][1], qa[1][kc][2], qa[1][kc][3], b0, b1);
            }
        }

        // Online softmax (rows live across 4 quad lanes)
        #pragma unroll
        for (int mi = 0; mi < 2; mi++) {
            float mx0 = -1e30f, mx1 = -1e30f;
            #pragma unroll
            for (int ni = 0; ni < 8; ni++) {
                mx0 = fmaxf(mx0, fmaxf(s[mi][ni][0], s[mi][ni][1]));
                mx1 = fmaxf(mx1, fmaxf(s[mi][ni][2], s[mi][ni][3]));
            }
            mx0 = fmaxf(mx0, __shfl_xor_sync(0xffffffffu, mx0, 1));
            mx0 = fmaxf(mx0, __shfl_xor_sync(0xffffffffu, mx0, 2));
            mx1 = fmaxf(mx1, __shfl_xor_sync(0xffffffffu, mx1, 1));
            mx1 = fmaxf(mx1, __shfl_xor_sync(0xffffffffu, mx1, 2));

            float newm0 = fmaxf(mrow[mi * 2], mx0);
            float newm1 = fmaxf(mrow[mi * 2 + 1], mx1);
            float corr0 = __expf(mrow[mi * 2] - newm0);
            float corr1 = __expf(mrow[mi * 2 + 1] - newm1);
            mrow[mi * 2] = newm0;
            mrow[mi * 2 + 1] = newm1;

            float ls0 = 0.f, ls1 = 0.f;
            int r = warp * 32 + mi * 16 + g;
            #pragma unroll
            for (int ni = 0; ni < 8; ni++) {
                float p0 = __expf(s[mi][ni][0] - newm0);
                float p1 = __expf(s[mi][ni][1] - newm0);
                float p2 = __expf(s[mi][ni][2] - newm1);
                float p3 = __expf(s[mi][ni][3] - newm1);
                ls0 += p0 + p1;
                ls1 += p2 + p3;
                // store P (tf32) at true key columns
                int c = ni * 8 + 2 * q;
                Ps[r * PPAD + c]           = f2tf32(p0);
                Ps[r * PPAD + c + 1]       = f2tf32(p1);
                Ps[(r + 8) * PPAD + c]     = f2tf32(p2);
                Ps[(r + 8) * PPAD + c + 1] = f2tf32(p3);
            }
            lrow[mi * 2]     = lrow[mi * 2] * corr0 + ls0;
            lrow[mi * 2 + 1] = lrow[mi * 2 + 1] * corr1 + ls1;
            #pragma unroll
            for (int ni = 0; ni < 4; ni++) {
                o[mi][ni][0] *= corr0; o[mi][ni][1] *= corr0;
                o[mi][ni][2] *= corr1; o[mi][ni][3] *= corr1;
            }
        }
        __syncwarp();

        // O += P * V : k = 64 keys, n = 32 d
        #pragma unroll
        for (int kj = 0; kj < 8; kj++) {
            unsigned pa[2][4];
            #pragma unroll
            for (int mi = 0; mi < 2; mi++) {
                int r = warp * 32 + mi * 16 + g;
                pa[mi][0] = __float_as_uint(Ps[r * PPAD + kj * 8 + q]);
                pa[mi][1] = __float_as_uint(Ps[(r + 8) * PPAD + kj * 8 + q]);
                pa[mi][2] = __float_as_uint(Ps[r * PPAD + kj * 8 + q + 4]);
                pa[mi][3] = __float_as_uint(Ps[(r + 8) * PPAD + kj * 8 + q + 4]);
            }
            #pragma unroll
            for (int ni = 0; ni < 4; ni++) {
                unsigned b0 = __float_as_uint(Vs[(kj * 8 + q) * KPAD + ni * 8 + g]);
                unsigned b1 = __float_as_uint(Vs[(kj * 8 + q + 4) * KPAD + ni * 8 + g]);
                mma_tf32(o[0][ni], pa[0][0], pa[0][1], pa[0][2], pa[0][3], b0, b1);
                mma_tf32(o[1][ni], pa[1][0], pa[1][1], pa[1][2], pa[1][3], b0, b1);
            }
        }
    }

    // Final row-sum reduce and normalize
    float linv[4];
    #pragma unroll
    for (int i = 0; i < 4; i++) {
        float l = lrow[i];
        l += __shfl_xor_sync(0xffffffffu, l, 1);
        l += __shfl_xor_sync(0xffffffffu, l, 2);
        linv[i] = 1.f / l;
    }

    // Stage O through smem (alias Qs) for coalesced store: Os[d][n_local]
    __syncthreads();
    float* Os = sm + QS_OFF;  // [32][OPAD]
    #pragma unroll
    for (int mi = 0; mi < 2; mi++) {
        int r = warp * 32 + mi * 16 + g;
        #pragma unroll
        for (int ni = 0; ni < 4; ni++) {
            int dcol = ni * 8 + 2 * q;
            Os[dcol * OPAD + r]             = o[mi][ni][0] * linv[mi * 2];
            Os[(dcol + 1) * OPAD + r]       = o[mi][ni][1] * linv[mi * 2];
            Os[dcol * OPAD + r + 8]         = o[mi][ni][2] * linv[mi * 2 + 1];
            Os[(dcol + 1) * OPAD + r + 8]   = o[mi][ni][3] * linv[mi * 2 + 1];
        }
    }
    __syncthreads();
    #pragma unroll
    for (int dd = 0; dd < 32; dd++) {
        g_AO[(bh * 32 + dd) * N_ + n0 + tid] = Os[dd * OPAD + tid];
    }
}

// ---------------------------------------------------------------------------
// Kernel 3: proj GEMM + bias + residual.  Y = Wp @ AO + bp + x
// ---------------------------------------------------------------------------
__global__ __launch_bounds__(256) void proj_gemm_kernel(
    const float* __restrict__ x, const float* __restrict__ W,
    const float* __restrict__ bias)
{
    __shared__ float As[64][16];
    __shared__ float Bs[16][64];

    const int b  = blockIdx.z;
    const int o0 = blockIdx.y * 64;
    const int n0 = blockIdx.x * 64;
    const int tid = threadIdx.x;
    const int tx = tid & 15, ty = tid >> 4;

    const float* ab = g_AO + b * (C_ * N_);
    float acc[4][4] = {};

    for (int kk = 0; kk < C_; kk += 16) {
        #pragma unroll
        for (int i = 0; i < 4; i++) {
            int lin = tid + i * 256;
            int m = lin >> 4, k = lin & 15;
            As[m][k] = W[(o0 + m) * C_ + kk + k];
        }
        #pragma unroll
        for (int i = 0; i < 4; i++) {
            int lin = tid + i * 256;
            int k = lin >> 6, n = lin & 63;
            Bs[k][n] = ab[(kk + k) * N_ + n0 + n];
        }
        __syncthreads();
        #pragma unroll
        for (int k = 0; k < 16; k++) {
            float4 bv = *(const float4*)&Bs[k][tx * 4];
            #pragma unroll
            for (int i = 0; i < 4; i++) {
                float a = As[ty * 4 + i][k];
                acc[i][0] += a * bv.x;
                acc[i][1] += a * bv.y;
                acc[i][2] += a * bv.z;
                acc[i][3] += a * bv.w;
            }
        }
        __syncthreads();
    }

    #pragma unroll
    for (int i = 0; i < 4; i++) {
        int o = o0 + ty * 4 + i;
        float bv = bias[o];
        const float* xr = x + b * (C_ * N_) + o * N_ + n0 + tx * 4;
        float4 xr4 = *(const float4*)xr;
        float* dst = g_Y + b * (C_ * N_) + o * N_ + n0 + tx * 4;
        float4 v;
        v.x = acc[i][0] + bv + xr4.x;
        v.y = acc[i][1] + bv + xr4.y;
        v.z = acc[i][2] + bv + xr4.z;
        v.w = acc[i][3] + bv + xr4.w;
        *(float4*)dst = v;
    }
}

// ---------------------------------------------------------------------------
// Kernel 4: LayerNorm over channels. Block: 32 n-cols x 8 c-groups.
// ---------------------------------------------------------------------------
__global__ __launch_bounds__(256) void ln_kernel(
    const float* __restrict__ ln_g, const float* __restrict__ ln_b,
    float* __restrict__ out)
{
    __shared__ float ssum[8][32], ssq[8][32];
    __shared__ float smu[32], srstd[32];

    const int batch = blockIdx.y;
    const int nc = threadIdx.x & 31;
    const int cg = threadIdx.x >> 5;
    const int n  = blockIdx.x * 32 + nc;
    const float* Yb = g_Y + batch * (C_ * N_) + n;

    float sum = 0.f, sq = 0.f;
    #pragma unroll 8
    for (int i = 0; i < 32; i++) {
        float v = Yb[(cg * 32 + i) * N_];
        sum += v; sq += v * v;
    }
    ssum[cg][nc] = sum; ssq[cg][nc] = sq;
    __syncthreads();
    if (cg == 0) {
        float s = 0.f, qq = 0.f;
        #pragma unroll
        for (int j = 0; j < 8; j++) { s += ssum[j][nc]; qq += ssq[j][nc]; }
        float mu = s * (1.f / C_);
        float var = qq * (1.f / C_) - mu * mu;
        smu[nc] = mu; srstd[nc] = rsqrtf(var + 1e-5f);
    }
    __syncthreads();
    float mu = smu[nc], rs = srstd[nc];
    float* ob = out + batch * (C_ * N_) + n;
    #pragma unroll 8
    for (int i = 0; i < 32; i++) {
        int c = cg * 32 + i;
        float v = Yb[c * N_];
        ob[c * N_] = (v - mu) * rs * ln_g[c] + ln_b[c];
    }
}

// ---------------------------------------------------------------------------
extern "C" void kernel_launch(void* const* d_in, const int* in_sizes, int n_in,
                              void* d_out, int out_size)
{
    const float* x      = (const float*)d_in[0];
    const float* w_qkv  = (const float*)d_in[1];
    const float* b_qkv  = (const float*)d_in[2];
    const float* w_proj = (const float*)d_in[3];
    const float* b_proj = (const float*)d_in[4];
    const float* ln_g   = (const float*)d_in[5];
    const float* ln_b   = (const float*)d_in[6];
    float* out = (float*)d_out;

    const size_t attn_smem = SMEM_FLOATS * sizeof(float);  // 72704 B
    cudaFuncSetAttribute(attn_kernel, cudaFuncAttributeMaxDynamicSharedMemorySize,
                         (int)attn_smem);

    qkv_gemm_kernel<<<dim3(N_ / 64, (3 * C_) / 64, B_), 256>>>(x, w_qkv, b_qkv);
    attn_kernel<<<dim3(N_ / 128, B_ * H_), 128, attn_smem>>>();
    proj_gemm_kernel<<<dim3(N_ / 64, C_ / 64, B_), 256>>>(x, w_proj, b_proj);
    ln_kernel<<<dim3(N_ / 32, B_), 256>>>(ln_g, ln_b, out);
}